// round 1
// baseline (speedup 1.0000x reference)
#include <cuda_runtime.h>
#include <math.h>
#include <stdint.h>

#define BS 8
#define NN 2048
#define IN_F 256
#define OUT_F 128
#define NROWS (BS * NN)   // 16384
#define NEG_BIG -1e32f

// ---------------- scratch (static __device__, no allocations) ----------------
__device__ float g_WT[IN_F * OUT_F];      // W transposed: [k][o]
__device__ float g_nodes[(size_t)NROWS * OUT_F]; // 8 MB
__device__ float g_fsrc[NROWS];
__device__ float g_fdstb[NROWS];          // f_dst + a_b folded

// ---------------- kernel 0: transpose W (128x256 -> 256x128) ----------------
__global__ void transpose_W_kernel(const float* __restrict__ W) {
    int i = blockIdx.x * blockDim.x + threadIdx.x; // 0..32767
    int o = i >> 8;          // 0..127
    int k = i & 255;         // 0..255
    g_WT[k * OUT_F + o] = W[i];
}

// ---------------- kernel 1: nodes = X @ W^T + b, plus f_src/f_dst ----------------
// block: 256 threads, handles 32 rows x 128 outs. K looped in 4 chunks of 64.
__global__ __launch_bounds__(256) void node_transform_kernel(
    const float* __restrict__ X,
    const float* __restrict__ Wb,
    const float* __restrict__ aw,
    const float* __restrict__ ab)
{
    __shared__ float sIn[32 * 64];    // 8 KB
    __shared__ float sW[64 * 128];    // 32 KB  (k-major, conflict-free float4 reads)

    const int t  = threadIdx.x;
    const int tx = t & 31;            // lane: 32 lanes x 4 outs = 128 outs
    const int ty = t >> 5;            // warp: 8 warps x 4 rows = 32 rows
    const int R0 = blockIdx.x * 32;

    float acc[4][4];
    #pragma unroll
    for (int i = 0; i < 4; i++)
        #pragma unroll
        for (int j = 0; j < 4; j++) acc[i][j] = 0.f;

    for (int kc = 0; kc < 4; kc++) {
        const int k0 = kc * 64;
        __syncthreads();
        // load input tile: 32 rows x 64 k  (512 float4, coalesced)
        #pragma unroll
        for (int j = 0; j < 2; j++) {
            int f4 = t + 256 * j;
            int rr = f4 >> 4, c4 = f4 & 15;
            *(float4*)&sIn[rr * 64 + c4 * 4] =
                *(const float4*)&X[(size_t)(R0 + rr) * IN_F + k0 + c4 * 4];
        }
        // load W tile (k-major from g_WT): 64 k x 128 o  (2048 float4, coalesced)
        #pragma unroll
        for (int j = 0; j < 8; j++) {
            int f4 = t + 256 * j;
            int kk = f4 >> 5, o4 = f4 & 31;
            *(float4*)&sW[kk * 128 + o4 * 4] =
                *(const float4*)&g_WT[(size_t)(k0 + kk) * OUT_F + o4 * 4];
        }
        __syncthreads();

        #pragma unroll
        for (int k4 = 0; k4 < 16; k4++) {
            float4 iv[4];
            #pragma unroll
            for (int i = 0; i < 4; i++)
                iv[i] = *(float4*)&sIn[(ty * 4 + i) * 64 + k4 * 4]; // broadcast
            #pragma unroll
            for (int kk = 0; kk < 4; kk++) {
                float4 wv = *(float4*)&sW[(k4 * 4 + kk) * 128 + tx * 4];
                #pragma unroll
                for (int i = 0; i < 4; i++) {
                    float xv = (kk == 0) ? iv[i].x : (kk == 1) ? iv[i].y
                             : (kk == 2) ? iv[i].z : iv[i].w;
                    acc[i][0] = fmaf(xv, wv.x, acc[i][0]);
                    acc[i][1] = fmaf(xv, wv.y, acc[i][1]);
                    acc[i][2] = fmaf(xv, wv.z, acc[i][2]);
                    acc[i][3] = fmaf(xv, wv.w, acc[i][3]);
                }
            }
        }
    }

    // epilogue: bias, store nodes, fused f_src / f_dst reductions
    float bb[4], a1[4], a2[4];
    #pragma unroll
    for (int j = 0; j < 4; j++) {
        bb[j] = Wb[tx * 4 + j];
        a1[j] = aw[tx * 4 + j];
        a2[j] = aw[OUT_F + tx * 4 + j];
    }
    const float abv = ab[0];

    #pragma unroll
    for (int i = 0; i < 4; i++) {
        #pragma unroll
        for (int j = 0; j < 4; j++) acc[i][j] += bb[j];
        const int row = R0 + ty * 4 + i;
        float4 ov = make_float4(acc[i][0], acc[i][1], acc[i][2], acc[i][3]);
        *(float4*)&g_nodes[(size_t)row * OUT_F + tx * 4] = ov;

        float ps = acc[i][0]*a1[0] + acc[i][1]*a1[1] + acc[i][2]*a1[2] + acc[i][3]*a1[3];
        float pd = acc[i][0]*a2[0] + acc[i][1]*a2[1] + acc[i][2]*a2[2] + acc[i][3]*a2[3];
        #pragma unroll
        for (int off = 16; off > 0; off >>= 1) {
            ps += __shfl_xor_sync(0xffffffffu, ps, off);
            pd += __shfl_xor_sync(0xffffffffu, pd, off);
        }
        if (tx == 0) {
            g_fsrc[row]  = ps;
            g_fdstb[row] = pd + abv;
        }
    }
}

// ---------------- kernel 2: flash-style masked softmax + PV ----------------
// grid: (32 row-tiles, 8 batches). block: 256 threads.
// Each block: 64 query rows x 128 outs, streaming 32 col-tiles of 64.
// Dynamic smem layout (floats):
//   nsh   [0      .. 8192)   : nodes col tile 64x128
//   adjsh [8192   .. 12352)  : adj tile 64x65 (padded, as int)
//   psh   [12352  .. 16704)  : p transposed, [c][r], row stride 68
//   fdsh  [16704  .. 16768)  : f_dst tile
//   msh   [16768  .. 16832)  : running max
//   lsh   [16832  .. 16896)  : running sum
//   rsh   [16896  .. 16960)  : rescale factor
#define SM_FLOATS 16960

__global__ __launch_bounds__(256) void gat_attn_kernel(
    const int* __restrict__ adj,
    float* __restrict__ out)
{
    extern __shared__ float sm[];
    float* nsh   = sm;
    int*   adjsh = (int*)(sm + 8192);
    float* psh   = sm + 12352;
    float* fdsh  = sm + 16704;
    float* msh   = sm + 16768;
    float* lsh   = sm + 16832;
    float* rsh   = sm + 16896;

    const int t  = threadIdx.x;
    const int b  = blockIdx.y;
    const int n0 = blockIdx.x * 64;

    // score-phase layout: 4 lanes per row
    const int sr  = t >> 2;
    const int sc0 = t & 3;
    // PV-phase layout: 16 row-groups x 16 out-groups
    const int rg = t >> 4;   // rows rg*4 .. rg*4+3
    const int og = t & 15;   // outs og*8 .. og*8+7

    if (t < 64) { msh[t] = -INFINITY; lsh[t] = 0.f; }

    float acc[4][8];
    #pragma unroll
    for (int i = 0; i < 4; i++)
        #pragma unroll
        for (int j = 0; j < 8; j++) acc[i][j] = 0.f;

    const float fs = g_fsrc[b * NN + n0 + sr];
    const int* adjb = adj + ((size_t)b * NN + n0) * NN;
    const float* nodesb = g_nodes + (size_t)b * NN * OUT_F;
    const float* fdb = g_fdstb + b * NN;

    for (int m0 = 0; m0 < NN; m0 += 64) {
        __syncthreads();   // prev PV done with nsh/psh

        // ---- load adj tile 64x64 (coalesced int4, store padded) ----
        #pragma unroll
        for (int j = 0; j < 4; j++) {
            int idx = t + 256 * j;
            int rr = idx >> 4, c4 = idx & 15;
            int4 av = *(const int4*)&adjb[(size_t)rr * NN + m0 + c4 * 4];
            int bo = rr * 65 + c4 * 4;
            adjsh[bo + 0] = av.x; adjsh[bo + 1] = av.y;
            adjsh[bo + 2] = av.z; adjsh[bo + 3] = av.w;
        }
        // ---- load nodes tile 64x128 (coalesced float4) ----
        #pragma unroll
        for (int j = 0; j < 8; j++) {
            int idx = t + 256 * j;
            int rr = idx >> 5, o4 = idx & 31;
            *(float4*)&nsh[rr * 128 + o4 * 4] =
                *(const float4*)&nodesb[(size_t)(m0 + rr) * OUT_F + o4 * 4];
        }
        if (t < 64) fdsh[t] = fdb[m0 + t];
        __syncthreads();

        // ---- score phase: leakyrelu + mask + online softmax ----
        float s[16];
        float lm = -INFINITY;
        #pragma unroll
        for (int k = 0; k < 16; k++) {
            int c = sc0 + 4 * k;
            float sc = fs + fdsh[c];
            sc = (sc >= 0.f) ? sc : 0.2f * sc;
            sc = (adjsh[sr * 65 + c] > 0) ? sc : NEG_BIG;
            s[k] = sc;
            lm = fmaxf(lm, sc);
        }
        lm = fmaxf(lm, __shfl_xor_sync(0xffffffffu, lm, 1));
        lm = fmaxf(lm, __shfl_xor_sync(0xffffffffu, lm, 2));
        const float mo = msh[sr];
        const float mn = fmaxf(mo, lm);
        float sum = 0.f;
        #pragma unroll
        for (int k = 0; k < 16; k++) {
            float p = __expf(s[k] - mn);
            psh[(sc0 + 4 * k) * 68 + sr] = p;
            sum += p;
        }
        sum += __shfl_xor_sync(0xffffffffu, sum, 1);
        sum += __shfl_xor_sync(0xffffffffu, sum, 2);
        if (sc0 == 0) {
            float rsc = __expf(mo - mn);   // -inf -> 0 on first tile
            rsh[sr] = rsc;
            lsh[sr] = lsh[sr] * rsc + sum;
            msh[sr] = mn;
        }
        __syncthreads();

        // ---- PV phase: acc = acc*rescale + P @ nodes_tile ----
        {
            float r0 = rsh[rg * 4 + 0], r1 = rsh[rg * 4 + 1];
            float r2 = rsh[rg * 4 + 2], r3 = rsh[rg * 4 + 3];
            #pragma unroll
            for (int j = 0; j < 8; j++) {
                acc[0][j] *= r0; acc[1][j] *= r1;
                acc[2][j] *= r2; acc[3][j] *= r3;
            }
        }
        #pragma unroll 4
        for (int c = 0; c < 64; c++) {
            float4 p4 = *(float4*)&psh[c * 68 + rg * 4];
            float4 nA = *(float4*)&nsh[c * 128 + og * 8];
            float4 nB = *(float4*)&nsh[c * 128 + og * 8 + 4];
            acc[0][0] = fmaf(p4.x, nA.x, acc[0][0]);
            acc[0][1] = fmaf(p4.x, nA.y, acc[0][1]);
            acc[0][2] = fmaf(p4.x, nA.z, acc[0][2]);
            acc[0][3] = fmaf(p4.x, nA.w, acc[0][3]);
            acc[0][4] = fmaf(p4.x, nB.x, acc[0][4]);
            acc[0][5] = fmaf(p4.x, nB.y, acc[0][5]);
            acc[0][6] = fmaf(p4.x, nB.z, acc[0][6]);
            acc[0][7] = fmaf(p4.x, nB.w, acc[0][7]);
            acc[1][0] = fmaf(p4.y, nA.x, acc[1][0]);
            acc[1][1] = fmaf(p4.y, nA.y, acc[1][1]);
            acc[1][2] = fmaf(p4.y, nA.z, acc[1][2]);
            acc[1][3] = fmaf(p4.y, nA.w, acc[1][3]);
            acc[1][4] = fmaf(p4.y, nB.x, acc[1][4]);
            acc[1][5] = fmaf(p4.y, nB.y, acc[1][5]);
            acc[1][6] = fmaf(p4.y, nB.z, acc[1][6]);
            acc[1][7] = fmaf(p4.y, nB.w, acc[1][7]);
            acc[2][0] = fmaf(p4.z, nA.x, acc[2][0]);
            acc[2][1] = fmaf(p4.z, nA.y, acc[2][1]);
            acc[2][2] = fmaf(p4.z, nA.z, acc[2][2]);
            acc[2][3] = fmaf(p4.z, nA.w, acc[2][3]);
            acc[2][4] = fmaf(p4.z, nB.x, acc[2][4]);
            acc[2][5] = fmaf(p4.z, nB.y, acc[2][5]);
            acc[2][6] = fmaf(p4.z, nB.z, acc[2][6]);
            acc[2][7] = fmaf(p4.z, nB.w, acc[2][7]);
            acc[3][0] = fmaf(p4.w, nA.x, acc[3][0]);
            acc[3][1] = fmaf(p4.w, nA.y, acc[3][1]);
            acc[3][2] = fmaf(p4.w, nA.z, acc[3][2]);
            acc[3][3] = fmaf(p4.w, nA.w, acc[3][3]);
            acc[3][4] = fmaf(p4.w, nB.x, acc[3][4]);
            acc[3][5] = fmaf(p4.w, nB.y, acc[3][5]);
            acc[3][6] = fmaf(p4.w, nB.z, acc[3][6]);
            acc[3][7] = fmaf(p4.w, nB.w, acc[3][7]);
        }
    }

    // ---- epilogue: divide by l, store ----
    #pragma unroll
    for (int i = 0; i < 4; i++) {
        float inv = 1.f / lsh[rg * 4 + i];
        float4 oA = make_float4(acc[i][0]*inv, acc[i][1]*inv, acc[i][2]*inv, acc[i][3]*inv);
        float4 oB = make_float4(acc[i][4]*inv, acc[i][5]*inv, acc[i][6]*inv, acc[i][7]*inv);
        size_t ro = ((size_t)b * NN + n0 + rg * 4 + i) * OUT_F + og * 8;
        *(float4*)&out[ro]     = oA;
        *(float4*)&out[ro + 4] = oB;
    }
}

// ---------------- launch ----------------
extern "C" void kernel_launch(void* const* d_in, const int* in_sizes, int n_in,
                              void* d_out, int out_size)
{
    const float* X   = (const float*)d_in[0];   // (8,2048,256) f32
    const int*   adj = (const int*)  d_in[1];   // (8,2048,2048) i32
    const float* Ww  = (const float*)d_in[2];   // (128,256) f32
    const float* Wb  = (const float*)d_in[3];   // (128,) f32
    const float* aw  = (const float*)d_in[4];   // (1,256) f32
    const float* ab  = (const float*)d_in[5];   // (1,) f32
    float* out = (float*)d_out;                 // (8,2048,128) f32

    static bool attr_set = false;
    if (!attr_set) {
        cudaFuncSetAttribute(gat_attn_kernel,
                             cudaFuncAttributeMaxDynamicSharedMemorySize,
                             SM_FLOATS * sizeof(float));
        attr_set = true;
    }

    transpose_W_kernel<<<128, 256>>>(Ww);
    node_transform_kernel<<<NROWS / 32, 256>>>(X, Wb, aw, ab);
    dim3 grid(NN / 64, BS);
    gat_attn_kernel<<<grid, 256, SM_FLOATS * sizeof(float)>>>(adj, out);
}

// round 3
// speedup vs baseline: 2.5064x; 2.5064x over previous
#include <cuda_runtime.h>
#include <math.h>
#include <stdint.h>

#define BS 8
#define NN 2048
#define IN_F 256
#define OUT_F 128
#define NROWS (BS * NN)   // 16384

// ---------------- scratch (static __device__, no allocations) ----------------
__device__ float g_WT[IN_F * OUT_F];             // W transposed: [k][o]
__device__ float g_nodes[(size_t)NROWS * OUT_F]; // 8 MB, tf32-rounded values
__device__ float g_fsrc[NROWS];
__device__ float g_fdstb[NROWS];                 // f_dst + a_b folded

// ---------------- kernel 0: transpose W (128x256 -> 256x128) ----------------
__global__ void transpose_W_kernel(const float* __restrict__ W) {
    int i = blockIdx.x * blockDim.x + threadIdx.x;
    int o = i >> 8;
    int k = i & 255;
    g_WT[k * OUT_F + o] = W[i];
}

// ---------------- kernel 1: nodes = X @ W^T + b, plus f_src/f_dst ----------------
__global__ __launch_bounds__(256) void node_transform_kernel(
    const float* __restrict__ X,
    const float* __restrict__ Wb,
    const float* __restrict__ aw,
    const float* __restrict__ ab)
{
    __shared__ float sIn[32 * 64];
    __shared__ float sW[64 * 128];

    const int t  = threadIdx.x;
    const int tx = t & 31;
    const int ty = t >> 5;
    const int R0 = blockIdx.x * 32;

    float acc[4][4];
    #pragma unroll
    for (int i = 0; i < 4; i++)
        #pragma unroll
        for (int j = 0; j < 4; j++) acc[i][j] = 0.f;

    for (int kc = 0; kc < 4; kc++) {
        const int k0 = kc * 64;
        __syncthreads();
        #pragma unroll
        for (int j = 0; j < 2; j++) {
            int f4 = t + 256 * j;
            int rr = f4 >> 4, c4 = f4 & 15;
            *(float4*)&sIn[rr * 64 + c4 * 4] =
                *(const float4*)&X[(size_t)(R0 + rr) * IN_F + k0 + c4 * 4];
        }
        #pragma unroll
        for (int j = 0; j < 8; j++) {
            int f4 = t + 256 * j;
            int kk = f4 >> 5, o4 = f4 & 31;
            *(float4*)&sW[kk * 128 + o4 * 4] =
                *(const float4*)&g_WT[(size_t)(k0 + kk) * OUT_F + o4 * 4];
        }
        __syncthreads();

        #pragma unroll
        for (int k4 = 0; k4 < 16; k4++) {
            float4 iv[4];
            #pragma unroll
            for (int i = 0; i < 4; i++)
                iv[i] = *(float4*)&sIn[(ty * 4 + i) * 64 + k4 * 4];
            #pragma unroll
            for (int kk = 0; kk < 4; kk++) {
                float4 wv = *(float4*)&sW[(k4 * 4 + kk) * 128 + tx * 4];
                #pragma unroll
                for (int i = 0; i < 4; i++) {
                    float xv = (kk == 0) ? iv[i].x : (kk == 1) ? iv[i].y
                             : (kk == 2) ? iv[i].z : iv[i].w;
                    acc[i][0] = fmaf(xv, wv.x, acc[i][0]);
                    acc[i][1] = fmaf(xv, wv.y, acc[i][1]);
                    acc[i][2] = fmaf(xv, wv.z, acc[i][2]);
                    acc[i][3] = fmaf(xv, wv.w, acc[i][3]);
                }
            }
        }
    }

    float bb[4], a1[4], a2[4];
    #pragma unroll
    for (int j = 0; j < 4; j++) {
        bb[j] = Wb[tx * 4 + j];
        a1[j] = aw[tx * 4 + j];
        a2[j] = aw[OUT_F + tx * 4 + j];
    }
    const float abv = ab[0];

    #pragma unroll
    for (int i = 0; i < 4; i++) {
        #pragma unroll
        for (int j = 0; j < 4; j++) acc[i][j] += bb[j];
        const int row = R0 + ty * 4 + i;

        // f reductions use FULL precision nodes (matches reference)
        float ps = acc[i][0]*a1[0] + acc[i][1]*a1[1] + acc[i][2]*a1[2] + acc[i][3]*a1[3];
        float pd = acc[i][0]*a2[0] + acc[i][1]*a2[1] + acc[i][2]*a2[2] + acc[i][3]*a2[3];
        #pragma unroll
        for (int off = 16; off > 0; off >>= 1) {
            ps += __shfl_xor_sync(0xffffffffu, ps, off);
            pd += __shfl_xor_sync(0xffffffffu, pd, off);
        }
        if (tx == 0) {
            g_fsrc[row]  = ps;
            g_fdstb[row] = pd + abv;
        }

        // store nodes rounded to tf32 (bit pattern valid as f32)
        uint4 sv;
        asm("cvt.rna.tf32.f32 %0, %1;" : "=r"(sv.x) : "f"(acc[i][0]));
        asm("cvt.rna.tf32.f32 %0, %1;" : "=r"(sv.y) : "f"(acc[i][1]));
        asm("cvt.rna.tf32.f32 %0, %1;" : "=r"(sv.z) : "f"(acc[i][2]));
        asm("cvt.rna.tf32.f32 %0, %1;" : "=r"(sv.w) : "f"(acc[i][3]));
        *(uint4*)&g_nodes[(size_t)row * OUT_F + tx * 4] = sv;
    }
}

// ---------------- kernel 2: masked softmax (no online max needed) + tf32 MMA PV ----
// grid (32 row-tiles, 8 batches), 256 threads (8 warps).
// Block computes 64 query rows x 128 outs, streaming 32 key-tiles of 64.
// smem (floats): nsh 64x136 (nodes tile, tf32 bits), psh 64x68 (P, tf32 bits),
//                fdsh 64, lsh 64
#define PS 68
#define NS 136
#define SM_F (64*NS + 64*PS + 64 + 64)   // 13184 floats = 52736 B

__global__ __launch_bounds__(256) void gat_attn_kernel(
    const int* __restrict__ adj,
    float* __restrict__ out)
{
    extern __shared__ float sm[];
    float*    nsh  = sm;
    float*    psh  = sm + 64 * NS;
    float*    fdsh = sm + 64 * NS + 64 * PS;
    float*    lsh  = fdsh + 64;
    uint32_t* nu   = (uint32_t*)nsh;
    uint32_t* pu   = (uint32_t*)psh;

    const int t  = threadIdx.x;
    const int b  = blockIdx.y;
    const int n0 = blockIdx.x * 64;

    // score-phase mapping: 4 lanes per row, 16 contiguous cols each
    const int sr = t >> 2;
    const int c0 = (t & 3) * 16;
    // mma-phase mapping
    const int w   = t >> 5;
    const int wm  = w & 3;          // M group: rows wm*16..+16
    const int wn  = w >> 2;         // N half: cols wn*64..+64
    const int l   = t & 31;
    const int gid = l >> 2;
    const int tig = l & 3;

    float acc[8][4];
    #pragma unroll
    for (int nb = 0; nb < 8; nb++)
        #pragma unroll
        for (int j = 0; j < 4; j++) acc[nb][j] = 0.f;

    const float fs = g_fsrc[b * NN + n0 + sr];
    const int*   adjr   = adj + ((size_t)b * NN + n0 + sr) * NN + c0;
    const float* nodesb = g_nodes + (size_t)b * NN * OUT_F;
    const float* fdb    = g_fdstb + b * NN;
    float lsum = 0.f;

    for (int m0 = 0; m0 < NN; m0 += 64) {
        // adjacency for this thread's 16 cols: 4 x int4, contiguous per thread
        int4 av[4];
        #pragma unroll
        for (int j = 0; j < 4; j++)
            av[j] = *(const int4*)&adjr[m0 + 4 * j];

        __syncthreads();   // previous tile's mma done reading nsh/psh

        // ---- stage nodes tile 64x128 (tf32 bit patterns) ----
        #pragma unroll
        for (int j = 0; j < 8; j++) {
            int idx = t + 256 * j;
            int rr = idx >> 5, o4 = idx & 31;
            *(float4*)&nsh[rr * NS + o4 * 4] =
                *(const float4*)&nodesb[(size_t)(m0 + rr) * OUT_F + o4 * 4];
        }
        if (t < 16) *(float4*)&fdsh[t * 4] = *(const float4*)&fdb[m0 + t * 4];
        __syncthreads();

        // ---- scores -> p = exp(leakyrelu(s)) * mask ; write tf32 P ----
        #pragma unroll
        for (int j = 0; j < 4; j++) {
            float4 fd4 = *(float4*)&fdsh[c0 + 4 * j];
            uint4 pv;
            float s, p;
            s = fs + fd4.x; s = (s >= 0.f) ? s : 0.2f * s;
            p = (av[j].x > 0) ? __expf(s) : 0.f; lsum += p;
            asm("cvt.rna.tf32.f32 %0, %1;" : "=r"(pv.x) : "f"(p));
            s = fs + fd4.y; s = (s >= 0.f) ? s : 0.2f * s;
            p = (av[j].y > 0) ? __expf(s) : 0.f; lsum += p;
            asm("cvt.rna.tf32.f32 %0, %1;" : "=r"(pv.y) : "f"(p));
            s = fs + fd4.z; s = (s >= 0.f) ? s : 0.2f * s;
            p = (av[j].z > 0) ? __expf(s) : 0.f; lsum += p;
            asm("cvt.rna.tf32.f32 %0, %1;" : "=r"(pv.z) : "f"(p));
            s = fs + fd4.w; s = (s >= 0.f) ? s : 0.2f * s;
            p = (av[j].w > 0) ? __expf(s) : 0.f; lsum += p;
            asm("cvt.rna.tf32.f32 %0, %1;" : "=r"(pv.w) : "f"(p));
            *(uint4*)&pu[sr * PS + c0 + 4 * j] = pv;
        }
        __syncthreads();

        // ---- PV: acc += P(16x64 per warp-row-group) @ N(64x64 per warp-col-half) ----
        #pragma unroll
        for (int kc = 0; kc < 8; kc++) {
            const int k0 = kc * 8;
            uint32_t a0 = pu[(wm * 16 + gid)     * PS + k0 + tig];
            uint32_t a1 = pu[(wm * 16 + gid + 8) * PS + k0 + tig];
            uint32_t a2 = pu[(wm * 16 + gid)     * PS + k0 + tig + 4];
            uint32_t a3 = pu[(wm * 16 + gid + 8) * PS + k0 + tig + 4];
            #pragma unroll
            for (int nb = 0; nb < 8; nb++) {
                uint32_t b0 = nu[(k0 + tig)     * NS + wn * 64 + nb * 8 + gid];
                uint32_t b1 = nu[(k0 + tig + 4) * NS + wn * 64 + nb * 8 + gid];
                asm volatile(
                    "mma.sync.aligned.m16n8k8.row.col.f32.tf32.tf32.f32 "
                    "{%0,%1,%2,%3}, {%4,%5,%6,%7}, {%8,%9}, {%0,%1,%2,%3};\n"
                    : "+f"(acc[nb][0]), "+f"(acc[nb][1]),
                      "+f"(acc[nb][2]), "+f"(acc[nb][3])
                    : "r"(a0), "r"(a1), "r"(a2), "r"(a3), "r"(b0), "r"(b1));
            }
        }
    }

    // ---- row sums: reduce the 4 lanes covering each row ----
    lsum += __shfl_xor_sync(0xffffffffu, lsum, 1);
    lsum += __shfl_xor_sync(0xffffffffu, lsum, 2);
    if ((t & 3) == 0) lsh[sr] = lsum;
    __syncthreads();

    // ---- epilogue: divide by l, store ----
    {
        const int r0 = wm * 16 + gid;
        const int r1 = r0 + 8;
        float l0 = lsh[r0], l1 = lsh[r1];
        float inv0 = (l0 > 0.f) ? 1.f / l0 : 0.f;
        float inv1 = (l1 > 0.f) ? 1.f / l1 : 0.f;
        #pragma unroll
        for (int nb = 0; nb < 8; nb++) {
            int col = wn * 64 + nb * 8 + tig * 2;
            size_t ro0 = ((size_t)b * NN + n0 + r0) * OUT_F + col;
            size_t ro1 = ((size_t)b * NN + n0 + r1) * OUT_F + col;
            *(float2*)&out[ro0] = make_float2(acc[nb][0] * inv0, acc[nb][1] * inv0);
            *(float2*)&out[ro1] = make_float2(acc[nb][2] * inv1, acc[nb][3] * inv1);
        }
    }
}

// ---------------- launch ----------------
extern "C" void kernel_launch(void* const* d_in, const int* in_sizes, int n_in,
                              void* d_out, int out_size)
{
    const float* X   = (const float*)d_in[0];
    const int*   adj = (const int*)  d_in[1];
    const float* Ww  = (const float*)d_in[2];
    const float* Wb  = (const float*)d_in[3];
    const float* aw  = (const float*)d_in[4];
    const float* ab  = (const float*)d_in[5];
    float* out = (float*)d_out;

    static bool attr_set = false;
    if (!attr_set) {
        cudaFuncSetAttribute(gat_attn_kernel,
                             cudaFuncAttributeMaxDynamicSharedMemorySize,
                             SM_F * sizeof(float));
        attr_set = true;
    }

    transpose_W_kernel<<<128, 256>>>(Ww);
    node_transform_kernel<<<NROWS / 32, 256>>>(X, Wb, aw, ab);
    dim3 grid(NN / 64, BS);
    gat_attn_kernel<<<grid, 256, SM_F * sizeof(float)>>>(adj, out);
}